// round 9
// baseline (speedup 1.0000x reference)
#include <cuda_runtime.h>

#define NLEV 5
#define BATCH 128
#define NBOX 64

static __constant__ int c_Hc[NLEV] = {334, 167, 84, 42, 21};
static __constant__ int c_Wc[NLEV] = {200, 100, 50, 25, 13};

// float4 counts per level: (128*H*W)/4
#define N4_0 2137600
#define N4_1 534400
#define N4_2 134400
#define N4_3 33600
#define N4_4 8736

// Per-warp span: 10 unrolled lane-loads * 32 lanes = 320 float4 = 5 KB.
#define ULOADS 10
#define WARP_SPAN (32 * ULOADS)
#define WS0 0
#define WS1 6680
#define WS2 8350
#define WS3 8770
#define WS4 8875
#define WSE 8903

// Count blocks: level 0 split into 2 half-height blocks per batch.
//   blocks [0, 256)   : level 0, task = bx>>1, half = bx&1
//   blocks [256, 768) : levels 1-4, one (lev,b) each
#define CNT_BLOCKS   768
#define TOTAL_BLOCKS 1184             // one full wave at 8 blocks/SM
#define THREADS      256
#define NWARP        (THREADS / 32)

__device__ float        p_sum[NLEV * TOTAL_BLOCKS];
__device__ unsigned int p_cnt[CNT_BLOCKS];
__device__ unsigned int g_done;   // zero at load; reset by last block

// ---------------------------------------------------------------------------
template <typename T>
__device__ __forceinline__ T block_reduce_sum(T val) {
    __shared__ T sh[32];
    int lane = threadIdx.x & 31;
    int wid  = threadIdx.x >> 5;
#pragma unroll
    for (int o = 16; o > 0; o >>= 1) val += __shfl_down_sync(0xffffffffu, val, o);
    if (lane == 0) sh[wid] = val;
    __syncthreads();
    T r = (threadIdx.x < (unsigned)NWARP) ? sh[lane] : T(0);
    if (wid == 0) {
#pragma unroll
        for (int o = 16; o > 0; o >>= 1) r += __shfl_down_sync(0xffffffffu, r, o);
    }
    __syncthreads();
    return r;
}

// ---------------------------------------------------------------------------
// Count rows [row0, row1) of one (level, batch): atomics-free.
// Each row-thread scans the 64 packed y-intervals (LDS broadcast) to build a
// 64-bit active bitmap in registers, then ORs precomputed x-masks via ffs.
// sb layout (u32): x-masks [64*STRIDE] | packed y12 [64]
// ---------------------------------------------------------------------------
template <int H, int W>
__device__ __forceinline__ unsigned int do_count_rows(
    const float* __restrict__ boxes, int b, int row0, int row1,
    unsigned int* sb) {
    constexpr int   NW     = (W + 31) / 32;
    constexpr int   STRIDE = (NW | 1);
    constexpr float sx     = (float)(W / 800.0);
    constexpr float sy     = (float)(H / 1333.0);

    unsigned int* s_xm  = sb;
    unsigned int* s_y12 = sb + NBOX * STRIDE;
    int tid = threadIdx.x;

    if (tid < NBOX) {
        const float* bp = boxes + ((size_t)b * NBOX + tid) * 4;
        float fx1 = fminf(fmaxf(rintf(bp[0] * sx), 0.0f), (float)(W - 1));
        float fy1 = fminf(fmaxf(rintf(bp[1] * sy), 0.0f), (float)(H - 1));
        float fx2 = fminf(fmaxf(rintf(bp[2] * sx), 0.0f), (float)W);
        float fy2 = fminf(fmaxf(rintf(bp[3] * sy), 0.0f), (float)H);
        int ix1 = (int)fx1, iy1 = (int)fy1, ix2 = (int)fx2, iy2 = (int)fy2;
        bool valid = (fx2 > fx1) && (fy2 > fy1);

#pragma unroll
        for (int wi = 0; wi < NW; wi++) {
            int lo = ix1 - wi * 32;
            int hi = ix2 - wi * 32;
            lo = lo < 0 ? 0 : lo;
            hi = hi > 32 ? 32 : hi;
            unsigned int wmask = 0u;
            if (hi > lo) {
                unsigned int hm = (hi == 32) ? 0xFFFFFFFFu : ((1u << hi) - 1u);
                wmask = hm & (0xFFFFFFFFu << lo);
            }
            s_xm[tid * STRIDE + wi] = wmask;
        }
        // packed interval; invalid -> 0 (never active)
        s_y12[tid] = valid ? (((unsigned)iy1 << 16) | (unsigned)iy2) : 0u;
    }
    __syncthreads();

    int r = row0 + tid;
    unsigned int cnt = 0;
    if (r < row1) {
        unsigned int mlo = 0u, mhi = 0u;
#pragma unroll 8
        for (int m = 0; m < 32; m++) {
            unsigned int y12 = s_y12[m];               // broadcast
            bool act = ((unsigned)r >= (y12 >> 16)) &
                       ((unsigned)r < (y12 & 0xFFFFu));
            mlo |= (unsigned int)act << m;
        }
#pragma unroll 8
        for (int m = 0; m < 32; m++) {
            unsigned int y12 = s_y12[m + 32];
            bool act = ((unsigned)r >= (y12 >> 16)) &
                       ((unsigned)r < (y12 & 0xFFFFu));
            mhi |= (unsigned int)act << m;
        }

        unsigned int w[NW];
#pragma unroll
        for (int wi = 0; wi < NW; wi++) w[wi] = 0u;
        while (mlo) {
            int m = __ffs(mlo) - 1;
            mlo &= mlo - 1;
            const unsigned int* bm = &s_xm[m * STRIDE];
#pragma unroll
            for (int wi = 0; wi < NW; wi++) w[wi] |= bm[wi];
        }
        while (mhi) {
            int m = __ffs(mhi) - 1 + 32;
            mhi &= mhi - 1;
            const unsigned int* bm = &s_xm[m * STRIDE];
#pragma unroll
            for (int wi = 0; wi < NW; wi++) w[wi] |= bm[wi];
        }
#pragma unroll
        for (int wi = 0; wi < NW; wi++) cnt += (unsigned)__popc(w[wi]);
    }
    __syncthreads();
    return cnt;
}

// shared scratch: max 64*7 + 64 = 512 u32 = 2 KB
__device__ __forceinline__ unsigned int* cnt_smem() {
    static __shared__ unsigned int buf[512];
    return buf;
}

// ---------------------------------------------------------------------------
__global__ void __launch_bounds__(THREADS, 8)
work_kernel(const float* __restrict__ h0, const float* __restrict__ h1,
            const float* __restrict__ h2, const float* __restrict__ h3,
            const float* __restrict__ h4, const float* __restrict__ boxes,
            float* __restrict__ out) {
    int bx   = blockIdx.x;
    int tid  = threadIdx.x;
    int lane = tid & 31;
    int wid  = tid >> 5;

    // ============ sum phase: static contiguous per-warp partition ==========
    __shared__ float s_wsum[NWARP];
    __shared__ int   s_wlev[NWARP];
    {
        int g = bx * NWARP + wid;      // global warp id
        float s = 0.0f;
        int lev = -1;
        if (g < WSE) {
            lev = (g < WS1) ? 0 : (g < WS2) ? 1 : (g < WS3) ? 2
                : (g < WS4) ? 3 : 4;
            const float* hp = (lev == 0) ? h0 : (lev == 1) ? h1
                            : (lev == 2) ? h2 : (lev == 3) ? h3 : h4;
            int start = (lev == 0) ? WS0 : (lev == 1) ? WS1
                      : (lev == 2) ? WS2 : (lev == 3) ? WS3 : WS4;
            int n4    = (lev == 0) ? N4_0 : (lev == 1) ? N4_1
                      : (lev == 2) ? N4_2 : (lev == 3) ? N4_3 : N4_4;
            const float4* p = reinterpret_cast<const float4*>(hp);
            int idx0 = (g - start) * WARP_SPAN + lane;
            float a0 = 0.0f, a1 = 0.0f, a2 = 0.0f, a3 = 0.0f;
#pragma unroll
            for (int u = 0; u < ULOADS; u += 2) {
                int i0 = idx0 + u * 32;
                int i1 = idx0 + (u + 1) * 32;
                float4 v0 = (i0 < n4) ? p[i0] : make_float4(0.f, 0.f, 0.f, 0.f);
                float4 v1 = (i1 < n4) ? p[i1] : make_float4(0.f, 0.f, 0.f, 0.f);
                a0 += v0.x + v0.y;
                a1 += v0.z + v0.w;
                a2 += v1.x + v1.y;
                a3 += v1.z + v1.w;
            }
            s = (a0 + a1) + (a2 + a3);
#pragma unroll
            for (int o = 16; o > 0; o >>= 1)
                s += __shfl_down_sync(0xffffffffu, s, o);
        }
        if (lane == 0) { s_wsum[wid] = s; s_wlev[wid] = lev; }
        __syncthreads();
        if (tid == 0) {
            float acc0 = 0.f, acc1 = 0.f, acc2 = 0.f, acc3 = 0.f, acc4 = 0.f;
#pragma unroll
            for (int w2 = 0; w2 < NWARP; w2++) {
                int   l = s_wlev[w2];
                float v = s_wsum[w2];
                acc0 += (l == 0) ? v : 0.f;
                acc1 += (l == 1) ? v : 0.f;
                acc2 += (l == 2) ? v : 0.f;
                acc3 += (l == 3) ? v : 0.f;
                acc4 += (l == 4) ? v : 0.f;
            }
            p_sum[0 * TOTAL_BLOCKS + bx] = acc0;
            p_sum[1 * TOTAL_BLOCKS + bx] = acc1;
            p_sum[2 * TOTAL_BLOCKS + bx] = acc2;
            p_sum[3 * TOTAL_BLOCKS + bx] = acc3;
            p_sum[4 * TOTAL_BLOCKS + bx] = acc4;
        }
        __syncthreads();
    }

    // ============ count phase: blocks [0, 768) =============================
    if (bx < CNT_BLOCKS) {
        unsigned int* sb = cnt_smem();
        unsigned int cnt;
        if (bx < 256) {
            int b    = bx >> 1;
            int half = bx & 1;
            cnt = do_count_rows<334, 200>(boxes, b, half ? 167 : 0,
                                          half ? 334 : 167, sb);
        } else {
            int t   = bx - 256;
            int lev = 1 + (t >> 7);
            int b   = t & 127;
            switch (lev) {
                case 1:  cnt = do_count_rows<167, 100>(boxes, b, 0, 167, sb); break;
                case 2:  cnt = do_count_rows<84, 50>(boxes, b, 0, 84, sb);    break;
                case 3:  cnt = do_count_rows<42, 25>(boxes, b, 0, 42, sb);    break;
                default: cnt = do_count_rows<21, 13>(boxes, b, 0, 21, sb);    break;
            }
        }
        cnt = block_reduce_sum<unsigned int>(cnt);
        if (tid == 0) p_cnt[bx] = cnt;
    }

    // ============ completion ticket -> finalize ============================
    __shared__ bool is_last;
    __threadfence();
    if (tid == 0) {
        unsigned int v = atomicAdd(&g_done, 1u);
        is_last = (v == TOTAL_BLOCKS - 1);
    }
    __syncthreads();
    if (!is_last) return;
    __threadfence();

    __shared__ double s_d2[NLEV];
    if (wid < NLEV) {
        int lev = wid;
        double s = 0.0;
        for (int i = lane; i < TOTAL_BLOCKS; i += 32)
            s += (double)p_sum[lev * TOTAL_BLOCKS + i];
        unsigned int c = 0;
        if (lev == 0) {
            for (int i = lane; i < 256; i += 32) c += p_cnt[i];
        } else {
            for (int i = lane; i < BATCH; i += 32)
                c += p_cnt[256 + (lev - 1) * BATCH + i];
        }
#pragma unroll
        for (int o = 16; o > 0; o >>= 1) {
            s += __shfl_down_sync(0xffffffffu, s, o);
            c += __shfl_down_sync(0xffffffffu, c, o);
        }
        if (lane == 0) {
            double tn = (double)BATCH * (double)c_Hc[lev] * (double)c_Wc[lev];
            double d  = s / tn - (double)c / tn;
            s_d2[lev] = d * d;
        }
    }
    __syncthreads();
    if (tid == 0) {
        double acc = s_d2[0] + s_d2[1] + s_d2[2] + s_d2[3] + s_d2[4];
        out[0] = (float)(acc / (double)NLEV);
        atomicExch(&g_done, 0u);
    }
}

// ---------------------------------------------------------------------------
extern "C" void kernel_launch(void* const* d_in, const int* in_sizes, int n_in,
                              void* d_out, int out_size) {
    (void)in_sizes; (void)n_in; (void)out_size;
    const float* h0    = (const float*)d_in[0];
    const float* h1    = (const float*)d_in[1];
    const float* h2    = (const float*)d_in[2];
    const float* h3    = (const float*)d_in[3];
    const float* h4    = (const float*)d_in[4];
    const float* boxes = (const float*)d_in[5];
    float* out = (float*)d_out;

    work_kernel<<<TOTAL_BLOCKS, THREADS>>>(h0, h1, h2, h3, h4, boxes, out);
}

// round 10
// speedup vs baseline: 1.0865x; 1.0865x over previous
#include <cuda_runtime.h>
#include <cstdint>

#define NLEV 5
#define BATCH 128
#define NBOX 64

static __constant__ int c_Hc[NLEV] = {334, 167, 84, 42, 21};
static __constant__ int c_Wc[NLEV] = {200, 100, 50, 25, 13};

// float4 counts per level: (128*H*W)/4
#define N4_0 2137600
#define N4_1 534400
#define N4_2 134400
#define N4_3 33600
#define N4_4 8736

// Bulk-copy chunking: 512 float4 = 8192 B per chunk, per-level boundaries.
#define CH_F4 512
// chunk-index bases per level (ceil(N4/512) cumulative)
#define CB1 4175
#define CB2 5219
#define CB3 5482
#define CB4 5548
#define CBE 5566           // total chunks
// 5566 = 4*1184 + 830 -> blocks < 830 own 5 chunks, rest own 4
#define RICH_BLOCKS 830

#define CNT_BLOCKS   640
#define TOTAL_BLOCKS 1184   // one wave at 8 blocks/SM
#define THREADS      256
#define NWARP        8

__device__ float        p_sum[NLEV * TOTAL_BLOCKS];
__device__ unsigned int p_cnt[CNT_BLOCKS];
__device__ unsigned int g_done;   // zero at load; reset by last block

// ---------------------------------------------------------------------------
__device__ __forceinline__ uint32_t smem_u32(const void* p) {
    uint32_t a;
    asm("{ .reg .u64 t; cvta.to.shared.u64 t, %1; cvt.u32.u64 %0, t; }"
        : "=r"(a) : "l"(p));
    return a;
}

__device__ __forceinline__ void mbar_init(uint32_t mbar, uint32_t count) {
    asm volatile("mbarrier.init.shared.b64 [%0], %1;" :: "r"(mbar), "r"(count)
                 : "memory");
}

__device__ __forceinline__ void mbar_expect_tx(uint32_t mbar, uint32_t bytes) {
    asm volatile("mbarrier.arrive.expect_tx.shared.b64 _, [%0], %1;"
                 :: "r"(mbar), "r"(bytes) : "memory");
}

__device__ __forceinline__ void mbar_wait(uint32_t mbar, uint32_t parity) {
    uint32_t done;
    do {
        asm volatile(
            "{\n\t.reg .pred p;\n\t"
            "mbarrier.try_wait.parity.acquire.cta.shared::cta.b64 p, [%1], %2;\n\t"
            "selp.b32 %0, 1, 0, p;\n\t}"
            : "=r"(done) : "r"(mbar), "r"(parity) : "memory");
    } while (!done);
}

// 1D bulk async copy gmem -> CTA smem, completion via mbarrier tx bytes.
__device__ __forceinline__ void bulk_ld(uint32_t dst_smem, const void* src,
                                        uint32_t bytes, uint32_t mbar) {
    asm volatile(
        "cp.async.bulk.shared::cluster.global.mbarrier::complete_tx::bytes "
        "[%0], [%1], %2, [%3];"
        :: "r"(dst_smem), "l"(src), "r"(bytes), "r"(mbar) : "memory");
}

// chunk index -> (level, float4 offset, float4 size)
__device__ __forceinline__ void chunk_desc(int c, int& lev, int& off, int& sz) {
    int base, n4;
    if (c < CB1)      { lev = 0; base = 0;   n4 = N4_0; }
    else if (c < CB2) { lev = 1; base = CB1; n4 = N4_1; }
    else if (c < CB3) { lev = 2; base = CB2; n4 = N4_2; }
    else if (c < CB4) { lev = 3; base = CB3; n4 = N4_3; }
    else              { lev = 4; base = CB4; n4 = N4_4; }
    off = (c - base) * CH_F4;
    sz  = n4 - off;
    if (sz > CH_F4) sz = CH_F4;
}

// ---------------------------------------------------------------------------
template <typename T>
__device__ __forceinline__ T block_reduce_sum(T val) {
    __shared__ T sh[32];
    int lane = threadIdx.x & 31;
    int wid  = threadIdx.x >> 5;
#pragma unroll
    for (int o = 16; o > 0; o >>= 1) val += __shfl_down_sync(0xffffffffu, val, o);
    if (lane == 0) sh[wid] = val;
    __syncthreads();
    T r = (threadIdx.x < (unsigned)NWARP) ? sh[lane] : T(0);
    if (wid == 0) {
#pragma unroll
        for (int o = 16; o > 0; o >>= 1) r += __shfl_down_sync(0xffffffffu, r, o);
    }
    __syncthreads();
    return r;
}

// ---------------------------------------------------------------------------
// Exact union-coverage count (round-8 champion: per-box x-masks + per-row
// active-box bitmaps via shared atomicOr, then ffs-driven OR).
// sb layout (u32): x-masks [64*STRIDE] | act_lo[H] | act_hi[H]
// ---------------------------------------------------------------------------
template <int H, int W>
__device__ __forceinline__ unsigned int do_count(const float* __restrict__ boxes,
                                                 int b, unsigned int* sb) {
    constexpr int   NW     = (W + 31) / 32;
    constexpr int   STRIDE = (NW | 1);
    constexpr float sx     = (float)(W / 800.0);
    constexpr float sy     = (float)(H / 1333.0);

    unsigned int* s_xm = sb;
    unsigned int* s_lo = sb + NBOX * STRIDE;
    unsigned int* s_hi = s_lo + H;
    int tid = threadIdx.x;

    for (int i = tid; i < 2 * H; i += THREADS) s_lo[i] = 0u;
    __syncthreads();

    if (tid < NBOX) {
        const float* bp = boxes + ((size_t)b * NBOX + tid) * 4;
        float fx1 = fminf(fmaxf(rintf(bp[0] * sx), 0.0f), (float)(W - 1));
        float fy1 = fminf(fmaxf(rintf(bp[1] * sy), 0.0f), (float)(H - 1));
        float fx2 = fminf(fmaxf(rintf(bp[2] * sx), 0.0f), (float)W);
        float fy2 = fminf(fmaxf(rintf(bp[3] * sy), 0.0f), (float)H);
        int ix1 = (int)fx1, iy1 = (int)fy1, ix2 = (int)fx2, iy2 = (int)fy2;
        bool valid = (fx2 > fx1) && (fy2 > fy1);

#pragma unroll
        for (int wi = 0; wi < NW; wi++) {
            int lo = ix1 - wi * 32;
            int hi = ix2 - wi * 32;
            lo = lo < 0 ? 0 : lo;
            hi = hi > 32 ? 32 : hi;
            unsigned int wmask = 0u;
            if (hi > lo) {
                unsigned int hm = (hi == 32) ? 0xFFFFFFFFu : ((1u << hi) - 1u);
                wmask = hm & (0xFFFFFFFFu << lo);
            }
            s_xm[tid * STRIDE + wi] = wmask;
        }

        if (valid) {
            unsigned int  bit = 1u << (tid & 31);
            unsigned int* tgt = (tid < 32) ? s_lo : s_hi;
            for (int r = iy1; r < iy2; r++) atomicOr(&tgt[r], bit);
        }
    }
    __syncthreads();

    unsigned int cnt = 0;
    for (int r = tid; r < H; r += THREADS) {
        unsigned int w[NW];
#pragma unroll
        for (int wi = 0; wi < NW; wi++) w[wi] = 0u;
        unsigned int mlo = s_lo[r];
        unsigned int mhi = s_hi[r];
        while (mlo) {
            int m = __ffs(mlo) - 1;
            mlo &= mlo - 1;
            const unsigned int* bm = &s_xm[m * STRIDE];
#pragma unroll
            for (int wi = 0; wi < NW; wi++) w[wi] |= bm[wi];
        }
        while (mhi) {
            int m = __ffs(mhi) - 1 + 32;
            mhi &= mhi - 1;
            const unsigned int* bm = &s_xm[m * STRIDE];
#pragma unroll
            for (int wi = 0; wi < NW; wi++) w[wi] |= bm[wi];
        }
#pragma unroll
        for (int wi = 0; wi < NW; wi++) cnt += (unsigned)__popc(w[wi]);
    }
    __syncthreads();
    return cnt;
}

// ---------------------------------------------------------------------------
__global__ void __launch_bounds__(THREADS, 8)
work_kernel(const float* __restrict__ h0, const float* __restrict__ h1,
            const float* __restrict__ h2, const float* __restrict__ h3,
            const float* __restrict__ h4, const float* __restrict__ boxes,
            float* __restrict__ out) {
    // 2-stage bulk-copy ring (16 KB) — reused as count scratch afterwards.
    __shared__ __align__(16) float4 s_stage[2][CH_F4];
    __shared__ __align__(8)  unsigned long long s_mbar[2];
    __shared__ float s_red[NWARP][NLEV];

    int bx   = blockIdx.x;
    int tid  = threadIdx.x;
    int lane = tid & 31;
    int wid  = tid >> 5;

    const float* hp[NLEV] = {h0, h1, h2, h3, h4};
    uint32_t mb0 = smem_u32(&s_mbar[0]);
    uint32_t mb1 = smem_u32(&s_mbar[1]);

    if (tid == 0) { mbar_init(mb0, 1); mbar_init(mb1, 1); }
    __syncthreads();

    // ============ sum phase: bulk-async streamed chunks ====================
    int nch = (bx < RICH_BLOCKS) ? 5 : 4;

    if (tid == 0) {
#pragma unroll
        for (int k = 0; k < 2; k++) {
            int c = bx + k * TOTAL_BLOCKS;
            int lev, off, sz;
            chunk_desc(c, lev, off, sz);
            uint32_t bytes = (uint32_t)sz * 16u;
            uint32_t mb = k ? mb1 : mb0;
            mbar_expect_tx(mb, bytes);
            bulk_ld(smem_u32(&s_stage[k][0]),
                    (const char*)hp[lev] + (size_t)off * 16, bytes, mb);
        }
    }

    float a0 = 0.f, a1 = 0.f, a2 = 0.f, a3 = 0.f, a4 = 0.f;
    for (int k = 0; k < nch; k++) {
        int st = k & 1;
        int ph = (k >> 1) & 1;
        mbar_wait(st ? mb1 : mb0, ph);

        int c = bx + k * TOTAL_BLOCKS;
        int lev, off, sz;
        chunk_desc(c, lev, off, sz);

        float s = 0.f;
        if (tid < sz) {
            float4 v = s_stage[st][tid];
            s += (v.x + v.y) + (v.z + v.w);
        }
        if (tid + THREADS < sz) {
            float4 v = s_stage[st][tid + THREADS];
            s += (v.x + v.y) + (v.z + v.w);
        }
        switch (lev) {
            case 0: a0 += s; break;
            case 1: a1 += s; break;
            case 2: a2 += s; break;
            case 3: a3 += s; break;
            default: a4 += s; break;
        }
        __syncthreads();   // all consumed stage st -> safe to refill

        if (tid == 0 && k + 2 < nch) {
            int c2 = bx + (k + 2) * TOTAL_BLOCKS;
            int lev2, off2, sz2;
            chunk_desc(c2, lev2, off2, sz2);
            uint32_t bytes = (uint32_t)sz2 * 16u;
            uint32_t mb = st ? mb1 : mb0;
            mbar_expect_tx(mb, bytes);
            bulk_ld(smem_u32(&s_stage[st][0]),
                    (const char*)hp[lev2] + (size_t)off2 * 16, bytes, mb);
        }
    }

    // block-level per-level reduction
    {
        float v[NLEV] = {a0, a1, a2, a3, a4};
#pragma unroll
        for (int l = 0; l < NLEV; l++) {
#pragma unroll
            for (int o = 16; o > 0; o >>= 1)
                v[l] += __shfl_down_sync(0xffffffffu, v[l], o);
        }
        if (lane == 0) {
#pragma unroll
            for (int l = 0; l < NLEV; l++) s_red[wid][l] = v[l];
        }
        __syncthreads();
        if (tid == 0) {
#pragma unroll
            for (int l = 0; l < NLEV; l++) {
                float acc = 0.f;
#pragma unroll
                for (int w2 = 0; w2 < NWARP; w2++) acc += s_red[w2][l];
                p_sum[l * TOTAL_BLOCKS + bx] = acc;
            }
        }
        __syncthreads();
    }

    // ============ count phase: blocks [0, 640) =============================
    if (bx < CNT_BLOCKS) {
        unsigned int* sb = reinterpret_cast<unsigned int*>(&s_stage[0][0]);
        int lev = bx >> 7;
        int b   = bx & 127;
        unsigned int cnt;
        switch (lev) {
            case 0:  cnt = do_count<334, 200>(boxes, b, sb); break;
            case 1:  cnt = do_count<167, 100>(boxes, b, sb); break;
            case 2:  cnt = do_count<84, 50>(boxes, b, sb);   break;
            case 3:  cnt = do_count<42, 25>(boxes, b, sb);   break;
            default: cnt = do_count<21, 13>(boxes, b, sb);   break;
        }
        cnt = block_reduce_sum<unsigned int>(cnt);
        if (tid == 0) p_cnt[bx] = cnt;
    }

    // ============ completion ticket -> finalize ============================
    __shared__ bool is_last;
    __threadfence();
    if (tid == 0) {
        unsigned int v = atomicAdd(&g_done, 1u);
        is_last = (v == TOTAL_BLOCKS - 1);
    }
    __syncthreads();
    if (!is_last) return;
    __threadfence();

    __shared__ double s_d2[NLEV];
    if (wid < NLEV) {
        int lev = wid;
        double s = 0.0;
        for (int i = lane; i < TOTAL_BLOCKS; i += 32)
            s += (double)p_sum[lev * TOTAL_BLOCKS + i];
        unsigned int c = 0;
        for (int i = lane; i < BATCH; i += 32)
            c += p_cnt[lev * BATCH + i];
#pragma unroll
        for (int o = 16; o > 0; o >>= 1) {
            s += __shfl_down_sync(0xffffffffu, s, o);
            c += __shfl_down_sync(0xffffffffu, c, o);
        }
        if (lane == 0) {
            double tn = (double)BATCH * (double)c_Hc[lev] * (double)c_Wc[lev];
            double d  = s / tn - (double)c / tn;
            s_d2[lev] = d * d;
        }
    }
    __syncthreads();
    if (tid == 0) {
        double acc = s_d2[0] + s_d2[1] + s_d2[2] + s_d2[3] + s_d2[4];
        out[0] = (float)(acc / (double)NLEV);
        atomicExch(&g_done, 0u);
    }
}

// ---------------------------------------------------------------------------
extern "C" void kernel_launch(void* const* d_in, const int* in_sizes, int n_in,
                              void* d_out, int out_size) {
    (void)in_sizes; (void)n_in; (void)out_size;
    const float* h0    = (const float*)d_in[0];
    const float* h1    = (const float*)d_in[1];
    const float* h2    = (const float*)d_in[2];
    const float* h3    = (const float*)d_in[3];
    const float* h4    = (const float*)d_in[4];
    const float* boxes = (const float*)d_in[5];
    float* out = (float*)d_out;

    work_kernel<<<TOTAL_BLOCKS, THREADS>>>(h0, h1, h2, h3, h4, boxes, out);
}